// round 6
// baseline (speedup 1.0000x reference)
#include <cuda_runtime.h>
#include <cuda_fp16.h>
#include <cstdint>

#define DINL __device__ __forceinline__

constexpr int NROWS   = 65536;
constexpr int DFEAT   = 32;
constexpr int H       = 128;
constexpr int SPLITS  = 32;
constexpr int ROWS_PER_BLOCK = NROWS / SPLITS;   // 2048
constexpr int TILES   = ROWS_PER_BLOCK / 128;    // 16
constexpr int NTHREADS = 512;                    // 16 warps: 4 wm x 4 wn

// dynamic SMEM layout (bytes)
constexpr int SM_A0   = 0;          // A tile buf0: 128 rows x 256 B (swizzled)
constexpr int SM_A1   = 32768;
constexpr int SM_W1H  = 65536;      // 64 x uint32 (half2-packed W1)
constexpr int SM_B1H  = 65792;      // 64 x uint32
constexpr int SM_B2S  = 66048;      // 128 floats
constexpr int SM_W3S  = 66560;      // 128 floats
constexpr int SM_TOTAL = 67072;

DINL uint32_t smem_u32(const void* p) {
    uint32_t a;
    asm("{ .reg .u64 t; cvta.to.shared.u64 t, %1; cvt.u32.u64 %0, t; }"
        : "=r"(a) : "l"(p));
    return a;
}

DINL void ldsm_x4(uint32_t& a0, uint32_t& a1, uint32_t& a2, uint32_t& a3,
                  uint32_t addr) {
    asm volatile("ldmatrix.sync.aligned.m8n8.x4.shared.b16 {%0,%1,%2,%3}, [%4];"
                 : "=r"(a0), "=r"(a1), "=r"(a2), "=r"(a3) : "r"(addr));
}

DINL void mma16816(float* c, uint32_t a0, uint32_t a1, uint32_t a2, uint32_t a3,
                   uint32_t b0, uint32_t b1) {
    asm volatile(
        "mma.sync.aligned.m16n8k16.row.col.f32.f16.f16.f32 "
        "{%0,%1,%2,%3}, {%4,%5,%6,%7}, {%8,%9}, {%0,%1,%2,%3};"
        : "+f"(c[0]), "+f"(c[1]), "+f"(c[2]), "+f"(c[3])
        : "r"(a0), "r"(a1), "r"(a2), "r"(a3), "r"(b0), "r"(b1));
}

DINL uint32_t h2u(__half2 h) { return *reinterpret_cast<uint32_t*>(&h); }
DINL __half2 u2h(uint32_t u) { return *reinterpret_cast<__half2*>(&u); }

__global__ void __launch_bounds__(NTHREADS, 1)
kan_kernel(const float* __restrict__ x,  const float* __restrict__ W1,
           const float* __restrict__ b1, const float* __restrict__ W2,
           const float* __restrict__ b2, const float* __restrict__ W3,
           const float* __restrict__ b3, float* __restrict__ out)
{
    extern __shared__ char smem[];
    const uint32_t sb = smem_u32(smem);

    uint32_t* w1h = reinterpret_cast<uint32_t*>(smem + SM_W1H);
    uint32_t* b1h = reinterpret_cast<uint32_t*>(smem + SM_B1H);
    float*    b2s = reinterpret_cast<float*>(smem + SM_B2S);
    float*    w3s = reinterpret_cast<float*>(smem + SM_W3S);

    const int tid   = threadIdx.x;
    const int d     = blockIdx.x & (DFEAT - 1);   // feature fastest -> x L2 reuse
    const int split = blockIdx.x >> 5;
    const int n0    = split * ROWS_PER_BLOCK;

    const int lane = tid & 31, warp = tid >> 5;
    const int wm = warp & 3;        // 4 row-groups of 32
    const int wn = warp >> 2;       // 4 col-groups of 32
    const int tig = lane & 3, gid = lane >> 2;

    // ---- prologue: pack W1/b1 as half2 into SMEM; stage b2/W3 ----
    for (int i = tid; i < 64; i += NTHREADS) {
        w1h[i] = h2u(__floats2half2_rn(W1[d * H + 2 * i], W1[d * H + 2 * i + 1]));
        b1h[i] = h2u(__floats2half2_rn(b1[d * H + 2 * i], b1[d * H + 2 * i + 1]));
    }
    for (int i = tid; i < H; i += NTHREADS) {
        b2s[i] = b2[d * H + i];
        w3s[i] = W3[d * H + i];
    }
    const float b3d = b3[d];

    // ---- B (W2) fragments in registers, once per block ----
    uint32_t bfrag[8][4][2];
    {
        const float* w2d = W2 + (size_t)d * H * H;
        #pragma unroll
        for (int ks = 0; ks < 8; ++ks) {
            #pragma unroll
            for (int nf = 0; nf < 4; ++nf) {
                const int n  = wn * 32 + nf * 8 + gid;
                const int ka = ks * 16 + tig * 2;
                bfrag[ks][nf][0] = h2u(__floats2half2_rn(w2d[(ka    ) * H + n],
                                                         w2d[(ka + 1) * H + n]));
                bfrag[ks][nf][1] = h2u(__floats2half2_rn(w2d[(ka + 8) * H + n],
                                                         w2d[(ka + 9) * H + n]));
            }
        }
    }
    __syncthreads();   // weights visible before any produce

    const int prow  = tid >> 2;      // producer row (4 threads/row)
    const int pquad = tid & 3;       // 4 granules per thread
    const __half2 zero2 = __float2half2_rn(0.f);

    // produce one 8-col granule g of row prow into buffer A (half2 math)
    auto produce_granule = [&](char* A, uint32_t xh, int g) {
        const uint4 wv = *reinterpret_cast<const uint4*>(w1h + g * 4);
        const uint4 bv = *reinterpret_cast<const uint4*>(b1h + g * 4);
        const __half2 x2 = u2h(xh);
        uint4 u;
        u.x = h2u(__hmax2(__hfma2(x2, u2h(wv.x), u2h(bv.x)), zero2));
        u.y = h2u(__hmax2(__hfma2(x2, u2h(wv.y), u2h(bv.y)), zero2));
        u.z = h2u(__hmax2(__hfma2(x2, u2h(wv.z), u2h(bv.z)), zero2));
        u.w = h2u(__hmax2(__hfma2(x2, u2h(wv.w), u2h(bv.w)), zero2));
        const uint32_t byte = (uint32_t)prow * 256u
                            + (uint32_t)((g ^ (prow & 15)) << 4);
        *reinterpret_cast<uint4*>(A + byte) = u;
    };

    // produce tile 0 (each thread: 4 granules)
    {
        const float xv = x[(size_t)(n0 + prow) * DFEAT + d];
        const uint32_t xh = h2u(__half2half2(__float2half_rn(xv)));
        #pragma unroll
        for (int j = 0; j < 4; ++j)
            produce_granule(smem + SM_A0, xh, pquad * 4 + j);
    }
    __syncthreads();

    // ldmatrix lane-address components
    const int g2 = lane >> 3;
    const int ri = lane & 7;
    const int row_local = (g2 & 1) * 8 + ri;
    const int gran_hi   = g2 >> 1;

    for (int t = 0; t < TILES; ++t) {
        const int buf = t & 1;
        const uint32_t Abase = sb + (buf ? SM_A1 : SM_A0);
        char* Anext = smem + (buf ? SM_A0 : SM_A1);

        // prefetch next tile's x (consumed at ks>=4)
        float xnf = 0.f;
        const bool have_next = (t + 1 < TILES);
        if (have_next)
            xnf = x[(size_t)(n0 + (t + 1) * 128 + prow) * DFEAT + d];

        float acc[2][4][4];
        #pragma unroll
        for (int mf = 0; mf < 2; ++mf)
            #pragma unroll
            for (int nf = 0; nf < 4; ++nf)
                #pragma unroll
                for (int e = 0; e < 4; ++e) acc[mf][nf][e] = 0.f;

        uint32_t xh_next = 0;

        #pragma unroll
        for (int ks = 0; ks < 8; ++ks) {
            #pragma unroll
            for (int mf = 0; mf < 2; ++mf) {
                const int rowfull = wm * 32 + mf * 16 + row_local;
                const int gran    = ks * 2 + gran_hi;
                const uint32_t addr = Abase + (uint32_t)rowfull * 256u
                                    + (uint32_t)((gran ^ (rowfull & 15)) << 4);
                uint32_t a0, a1, a2, a3;
                ldsm_x4(a0, a1, a2, a3, addr);
                #pragma unroll
                for (int nf = 0; nf < 4; ++nf)
                    mma16816(acc[mf][nf], a0, a1, a2, a3,
                             bfrag[ks][nf][0], bfrag[ks][nf][1]);
            }
            // interleaved produce of next tile: 1 granule per ks, ks>=4
            if (ks >= 4 && have_next) {
                if (ks == 4)
                    xh_next = h2u(__half2half2(__float2half_rn(xnf)));
                produce_granule(Anext, xh_next, pquad * 4 + (ks - 4));
            }
        }

        // ---- epilogue: relu(acc + b2) * W3, shfl-reduce, direct atomicAdd ----
        #pragma unroll
        for (int mf = 0; mf < 2; ++mf) {
            float r0 = 0.f, r1 = 0.f;
            #pragma unroll
            for (int nf = 0; nf < 4; ++nf) {
                #pragma unroll
                for (int eb = 0; eb < 2; ++eb) {
                    const int col = wn * 32 + nf * 8 + tig * 2 + eb;
                    const float bb = b2s[col];
                    const float ww = w3s[col];
                    r0 += fmaxf(acc[mf][nf][eb]     + bb, 0.f) * ww;
                    r1 += fmaxf(acc[mf][nf][2 + eb] + bb, 0.f) * ww;
                }
            }
            r0 += __shfl_xor_sync(0xffffffffu, r0, 1);
            r0 += __shfl_xor_sync(0xffffffffu, r0, 2);
            r1 += __shfl_xor_sync(0xffffffffu, r1, 1);
            r1 += __shfl_xor_sync(0xffffffffu, r1, 2);
            if (tig == 0) {
                const int r = n0 + t * 128 + wm * 32 + mf * 16 + gid;
                const float bias = (wn == 0) ? b3d : 0.f;
                atomicAdd(out + r,     r0 + bias);
                atomicAdd(out + r + 8, r1 + bias);
            }
        }

        __syncthreads();   // A-buffer handoff
    }
}

extern "C" void kernel_launch(void* const* d_in, const int* in_sizes, int n_in,
                              void* d_out, int out_size) {
    const float* x  = (const float*)d_in[0];
    const float* W1 = (const float*)d_in[1];
    const float* b1 = (const float*)d_in[2];
    const float* W2 = (const float*)d_in[3];
    const float* b2 = (const float*)d_in[4];
    const float* W3 = (const float*)d_in[5];
    const float* b3 = (const float*)d_in[6];
    float* out = (float*)d_out;

    cudaFuncSetAttribute(kan_kernel, cudaFuncAttributeMaxDynamicSharedMemorySize,
                         SM_TOTAL);
    cudaMemsetAsync(d_out, 0, (size_t)out_size * sizeof(float), 0);
    kan_kernel<<<DFEAT * SPLITS, NTHREADS, SM_TOTAL>>>(x, W1, b1, W2, b2, W3, b3, out);
}

// round 8
// speedup vs baseline: 1.2423x; 1.2423x over previous
#include <cuda_runtime.h>
#include <cuda_fp16.h>
#include <cstdint>

#define DINL __device__ __forceinline__

constexpr int NROWS   = 65536;
constexpr int DFEAT   = 32;
constexpr int H       = 128;
constexpr int SPLITS  = 32;
constexpr int ROWS_PER_BLOCK = NROWS / SPLITS;   // 2048
constexpr int TILES   = ROWS_PER_BLOCK / 128;    // 16
constexpr int NTHREADS = 256;

// dynamic SMEM layout (bytes)
constexpr int SM_A0   = 0;          // A tile buf0: 128 rows x 256 B (swizzled)
constexpr int SM_A1   = 32768;
constexpr int SM_BF   = 65536;      // B frags: [ks8][nf4][wn4][lane32] uint2 = 32KB
constexpr int SM_W1H  = 98304;      // 64 x uint32 (half2-packed W1)
constexpr int SM_B1H  = 98560;      // 64 x uint32
constexpr int SM_B2S  = 98816;      // 128 floats
constexpr int SM_W3S  = 99328;      // 128 floats
constexpr int SM_TOTAL = 99840;     // x2 CTAs = 195.0 KB <= 228 KB

DINL uint32_t smem_u32(const void* p) {
    uint32_t a;
    asm("{ .reg .u64 t; cvta.to.shared.u64 t, %1; cvt.u32.u64 %0, t; }"
        : "=r"(a) : "l"(p));
    return a;
}

DINL void ldsm_x4(uint32_t& a0, uint32_t& a1, uint32_t& a2, uint32_t& a3,
                  uint32_t addr) {
    asm volatile("ldmatrix.sync.aligned.m8n8.x4.shared.b16 {%0,%1,%2,%3}, [%4];"
                 : "=r"(a0), "=r"(a1), "=r"(a2), "=r"(a3) : "r"(addr));
}

DINL void mma16816(float* c, uint32_t a0, uint32_t a1, uint32_t a2, uint32_t a3,
                   uint32_t b0, uint32_t b1) {
    asm volatile(
        "mma.sync.aligned.m16n8k16.row.col.f32.f16.f16.f32 "
        "{%0,%1,%2,%3}, {%4,%5,%6,%7}, {%8,%9}, {%0,%1,%2,%3};"
        : "+f"(c[0]), "+f"(c[1]), "+f"(c[2]), "+f"(c[3])
        : "r"(a0), "r"(a1), "r"(a2), "r"(a3), "r"(b0), "r"(b1));
}

DINL uint32_t h2u(__half2 h) { return *reinterpret_cast<uint32_t*>(&h); }
DINL __half2 u2h(uint32_t u) { return *reinterpret_cast<__half2*>(&u); }

__global__ void __launch_bounds__(NTHREADS, 2)
kan_kernel(const float* __restrict__ x,  const float* __restrict__ W1,
           const float* __restrict__ b1, const float* __restrict__ W2,
           const float* __restrict__ b2, const float* __restrict__ W3,
           const float* __restrict__ b3, float* __restrict__ out)
{
    extern __shared__ char smem[];
    const uint32_t sb = smem_u32(smem);

    uint2*    bfs = reinterpret_cast<uint2*>(smem + SM_BF);
    uint32_t* w1h = reinterpret_cast<uint32_t*>(smem + SM_W1H);
    uint32_t* b1h = reinterpret_cast<uint32_t*>(smem + SM_B1H);
    float*    b2s = reinterpret_cast<float*>(smem + SM_B2S);
    float*    w3s = reinterpret_cast<float*>(smem + SM_W3S);

    const int tid   = threadIdx.x;
    const int d     = blockIdx.x & (DFEAT - 1);   // feature fastest -> x L2 reuse
    const int split = blockIdx.x >> 5;
    const int n0    = split * ROWS_PER_BLOCK;

    const int lane = tid & 31, warp = tid >> 5;
    const int wm = warp & 1;        // 2 row-groups of 64
    const int wn = warp >> 1;       // 4 col-groups of 32
    const int tig = lane & 3, gid = lane >> 2;

    // ---- prologue: pack W1/b1 as half2; stage b2/W3; pack B frags to SMEM ----
    for (int i = tid; i < 64; i += NTHREADS) {
        w1h[i] = h2u(__floats2half2_rn(W1[d * H + 2 * i], W1[d * H + 2 * i + 1]));
        b1h[i] = h2u(__floats2half2_rn(b1[d * H + 2 * i], b1[d * H + 2 * i + 1]));
    }
    for (int i = tid; i < H; i += NTHREADS) {
        b2s[i] = b2[d * H + i];
        w3s[i] = W3[d * H + i];
    }
    const float b3d = b3[d];

    {
        const float* w2d = W2 + (size_t)d * H * H;
        for (int idx = tid; idx < 8 * 4 * 4 * 32; idx += NTHREADS) {
            const int ln  = idx & 31;
            const int wnn = (idx >> 5) & 3;
            const int nf  = (idx >> 7) & 3;
            const int ks  = idx >> 9;
            const int n   = wnn * 32 + nf * 8 + (ln >> 2);
            const int ka  = ks * 16 + (ln & 3) * 2;
            uint2 v;
            v.x = h2u(__floats2half2_rn(w2d[(ka    ) * H + n],
                                        w2d[(ka + 1) * H + n]));
            v.y = h2u(__floats2half2_rn(w2d[(ka + 8) * H + n],
                                        w2d[(ka + 9) * H + n]));
            bfs[idx] = v;
        }
    }
    __syncthreads();   // weights visible before any produce / mma

    const int prow  = tid >> 1;      // producer row (2 threads/row)
    const int phalf = tid & 1;
    const __half2 zero2 = __float2half2_rn(0.f);

    // produce one 8-col granule g of row prow into buffer A (half2 math)
    auto produce_granule = [&](char* A, uint32_t xh, int g) {
        const uint4 wv = *reinterpret_cast<const uint4*>(w1h + g * 4);
        const uint4 bv = *reinterpret_cast<const uint4*>(b1h + g * 4);
        const __half2 x2 = u2h(xh);
        uint4 u;
        u.x = h2u(__hmax2(__hfma2(x2, u2h(wv.x), u2h(bv.x)), zero2));
        u.y = h2u(__hmax2(__hfma2(x2, u2h(wv.y), u2h(bv.y)), zero2));
        u.z = h2u(__hmax2(__hfma2(x2, u2h(wv.z), u2h(bv.z)), zero2));
        u.w = h2u(__hmax2(__hfma2(x2, u2h(wv.w), u2h(bv.w)), zero2));
        const uint32_t byte = (uint32_t)prow * 256u
                            + (uint32_t)((g ^ (prow & 15)) << 4);
        *reinterpret_cast<uint4*>(A + byte) = u;
    };

    // produce tile 0
    {
        const float xv = x[(size_t)(n0 + prow) * DFEAT + d];
        const uint32_t xh = h2u(__half2half2(__float2half_rn(xv)));
        #pragma unroll
        for (int j = 0; j < 8; ++j)
            produce_granule(smem + SM_A0, xh, phalf * 8 + j);
    }
    __syncthreads();

    // epilogue constants per lane (registers, constant across tiles)
    float b2r[4][2], w3r[4][2];
    #pragma unroll
    for (int nf = 0; nf < 4; ++nf) {
        #pragma unroll
        for (int eb = 0; eb < 2; ++eb) {
            const int col = wn * 32 + nf * 8 + tig * 2 + eb;
            b2r[nf][eb] = b2s[col];
            w3r[nf][eb] = w3s[col];
        }
    }

    // B-frag SMEM index base for this warp: [ks][nf][wn][lane]
    const int bf_idx0 = wn * 32 + lane;

    // ldmatrix lane-address components
    const int g2 = lane >> 3;
    const int ri = lane & 7;
    const int row_local = (g2 & 1) * 8 + ri;
    const int gran_hi   = g2 >> 1;

    for (int t = 0; t < TILES; ++t) {
        const int buf = t & 1;
        const uint32_t Abase = sb + (buf ? SM_A1 : SM_A0);
        char* Anext = smem + (buf ? SM_A0 : SM_A1);

        // prefetch next tile's x (consumed at ks>=4)
        float xnf2 = 0.f;
        const bool have_next = (t + 1 < TILES);
        if (have_next)
            xnf2 = x[(size_t)(n0 + (t + 1) * 128 + prow) * DFEAT + d];

        float acc[4][4][4];
        #pragma unroll
        for (int mf = 0; mf < 4; ++mf)
            #pragma unroll
            for (int nf = 0; nf < 4; ++nf)
                #pragma unroll
                for (int e = 0; e < 4; ++e) acc[mf][nf][e] = 0.f;

        uint32_t xh_next = 0;

        #pragma unroll
        for (int ks = 0; ks < 8; ++ks) {
            // B fragments for this ks from SMEM (4 x LDS.64, conflict-free)
            uint2 bv[4];
            #pragma unroll
            for (int nf = 0; nf < 4; ++nf)
                bv[nf] = bfs[(ks * 4 + nf) * 128 + bf_idx0];

            #pragma unroll
            for (int mf = 0; mf < 4; ++mf) {
                const int rowfull = wm * 64 + mf * 16 + row_local;
                const int gran    = ks * 2 + gran_hi;
                const uint32_t addr = Abase + (uint32_t)rowfull * 256u
                                    + (uint32_t)((gran ^ (rowfull & 15)) << 4);
                uint32_t a0, a1, a2, a3;
                ldsm_x4(a0, a1, a2, a3, addr);
                #pragma unroll
                for (int nf = 0; nf < 4; ++nf)
                    mma16816(acc[mf][nf], a0, a1, a2, a3, bv[nf].x, bv[nf].y);
            }
            // interleaved produce of next tile: 2 granules per ks, ks>=4
            if (ks >= 4 && have_next) {
                if (ks == 4)
                    xh_next = h2u(__half2half2(__float2half_rn(xnf2)));
                const int j = (ks - 4) * 2;
                produce_granule(Anext, xh_next, phalf * 8 + j);
                produce_granule(Anext, xh_next, phalf * 8 + j + 1);
            }
        }

        // ---- epilogue: relu(acc + b2) * W3, shfl-reduce, direct atomicAdd ----
        #pragma unroll
        for (int mf = 0; mf < 4; ++mf) {
            float r0 = 0.f, r1 = 0.f;
            #pragma unroll
            for (int nf = 0; nf < 4; ++nf) {
                #pragma unroll
                for (int eb = 0; eb < 2; ++eb) {
                    r0 += fmaxf(acc[mf][nf][eb]     + b2r[nf][eb], 0.f) * w3r[nf][eb];
                    r1 += fmaxf(acc[mf][nf][2 + eb] + b2r[nf][eb], 0.f) * w3r[nf][eb];
                }
            }
            r0 += __shfl_xor_sync(0xffffffffu, r0, 1);
            r0 += __shfl_xor_sync(0xffffffffu, r0, 2);
            r1 += __shfl_xor_sync(0xffffffffu, r1, 1);
            r1 += __shfl_xor_sync(0xffffffffu, r1, 2);
            if (tig == 0) {
                const int r = n0 + t * 128 + wm * 64 + mf * 16 + gid;
                const float bias = (wn == 0) ? b3d : 0.f;
                atomicAdd(out + r,     r0 + bias);
                atomicAdd(out + r + 8, r1 + bias);
            }
        }

        __syncthreads();   // A-buffer handoff
    }
}

extern "C" void kernel_launch(void* const* d_in, const int* in_sizes, int n_in,
                              void* d_out, int out_size) {
    const float* x  = (const float*)d_in[0];
    const float* W1 = (const float*)d_in[1];
    const float* b1 = (const float*)d_in[2];
    const float* W2 = (const float*)d_in[3];
    const float* b2 = (const float*)d_in[4];
    const float* W3 = (const float*)d_in[5];
    const float* b3 = (const float*)d_in[6];
    float* out = (float*)d_out;

    cudaFuncSetAttribute(kan_kernel, cudaFuncAttributeMaxDynamicSharedMemorySize,
                         SM_TOTAL);
    cudaMemsetAsync(d_out, 0, (size_t)out_size * sizeof(float), 0);
    kan_kernel<<<DFEAT * SPLITS, NTHREADS, SM_TOTAL>>>(x, W1, b1, W2, b2, W3, b3, out);
}

// round 9
// speedup vs baseline: 1.5778x; 1.2701x over previous
#include <cuda_runtime.h>
#include <cstdint>

constexpr int NROWS  = 65536;
constexpr int DFEAT  = 32;
constexpr int H      = 128;
constexpr int NJ     = H + 1;          // 129 intervals
constexpr int SPLITS = 32;
constexpr int RPB    = NROWS / SPLITS; // 2048 rows per main CTA

// persistent scratch (static device globals — no runtime allocation)
__device__ float g_tab[DFEAT][NJ][2 * H];  // [d][j][ P(128) | Q+b2(128) ]
__device__ float g_kn [DFEAT][H];          // sorted knees per feature

// ---------------- precompute: build interval tables ----------------
// grid (32, 8): d = blockIdx.x, interval-chunk = blockIdx.y (17 intervals each)
__global__ void __launch_bounds__(512)
kan_precompute(const float* __restrict__ W1, const float* __restrict__ b1,
               const float* __restrict__ W2, const float* __restrict__ b2)
{
    extern __shared__ float ps[];
    float* W2s = ps;               // 16384 floats (64 KB)
    float* w1s = ps + H * H;       // 128
    float* b1s = w1s + H;          // 128
    float* b2s = b1s + H;          // 128
    float* kns = b2s + H;          // 128 (sorted knees)

    const int d   = blockIdx.x;
    const int jc  = blockIdx.y;
    const int tid = threadIdx.x;

    const float* w2d = W2 + (size_t)d * H * H;
    for (int i = tid; i < H * H / 4; i += 512)
        reinterpret_cast<float4*>(W2s)[i] =
            reinterpret_cast<const float4*>(w2d)[i];
    for (int i = tid; i < H; i += 512) {
        w1s[i] = W1[d * H + i];
        b1s[i] = b1[d * H + i];
        b2s[i] = b2[d * H + i];
    }
    __syncthreads();

    // knees + O(n^2) rank sort (exact, ties broken by index)
    if (tid < H) {
        const float w = w1s[tid], bb = b1s[tid];
        const float t = (w != 0.f) ? (-bb / w) : 3.0e38f;
        int rank = 0;
        for (int c = 0; c < H; ++c) {
            const float wc = w1s[c], bc = b1s[c];
            const float tc = (wc != 0.f) ? (-bc / wc) : 3.0e38f;
            rank += (tc < t) || ((tc == t) && (c < tid));
        }
        kns[rank] = t;
    }
    __syncthreads();
    if (jc == 0)
        for (int i = tid; i < H; i += 512) g_kn[d][i] = kns[i];

    // build P/Q for intervals in this chunk via midpoint evaluation
    const int j0 = jc * 17;
    const int j1 = min(NJ, j0 + 17);
    for (int idx = tid; idx < (j1 - j0) * H; idx += 512) {
        const int j = j0 + idx / H;
        const int k = idx - (idx / H) * H;
        float m;
        if (j == 0)       m = kns[0] - 1.0f;
        else if (j == H)  m = kns[H - 1] + 1.0f;
        else              m = 0.5f * (kns[j - 1] + kns[j]);
        float P = 0.f, Q = 0.f;
        #pragma unroll 4
        for (int c = 0; c < H; ++c) {
            const bool act = (m * w1s[c] + b1s[c]) > 0.f;
            const float wv = W2s[c * H + k];
            P = fmaf(act ? w1s[c] : 0.f, wv, P);
            Q = fmaf(act ? b1s[c] : 0.f, wv, Q);
        }
        g_tab[d][j][k]     = P;
        g_tab[d][j][H + k] = Q + b2s[k];  // fold b2 into Q
    }
}

// ---------------- main: per-row interval lookup + 128 FMA ----------------
// grid 1024 = (d fastest x 32 splits), 256 threads (8 warps)
// SMEM: table 129*256 + knees 128 + transpose 8*32*33 = 41600 floats
constexpr int SM_TAB   = 0;
constexpr int SM_KN    = NJ * 2 * H;            // 33024
constexpr int SM_TR    = SM_KN + H;             // 33152
constexpr int SM_FLOATS = SM_TR + 8 * 32 * 33;  // 41600
constexpr int MAIN_SMEM = SM_FLOATS * 4;        // 166400 B
constexpr int PRE_SMEM  = (H * H + 4 * H) * 4;  // 67584 B

__global__ void __launch_bounds__(256, 1)
kan_main(const float* __restrict__ x, const float* __restrict__ W3,
         const float* __restrict__ b3, float* __restrict__ out)
{
    extern __shared__ float s[];
    float* tabs  = s + SM_TAB;
    float* kns   = s + SM_KN;
    float* trans = s + SM_TR;

    const int tid   = threadIdx.x;
    const int d     = blockIdx.x & (DFEAT - 1);  // d fastest -> x L2 reuse
    const int split = blockIdx.x >> 5;
    const int n0    = split * RPB;
    const int lane  = tid & 31, w = tid >> 5;

    // load this feature's table + knees into SMEM
    {
        const float4* src = reinterpret_cast<const float4*>(&g_tab[d][0][0]);
        float4* dst = reinterpret_cast<float4*>(tabs);
        for (int i = tid; i < NJ * 2 * H / 4; i += 256) dst[i] = src[i];
        for (int i = tid; i < H; i += 256) kns[i] = g_kn[d][i];
    }
    __syncthreads();

    const float4 w3v = reinterpret_cast<const float4*>(W3 + d * H)[lane];
    const float  b3d = b3[d];
    float* tr = trans + w * (32 * 33);

    for (int b = 0; b < RPB / 256; ++b) {     // 8 batches of 32 rows per warp
        const int rowb = n0 + (b * 8 + w) * 32;

        // each lane owns one row: load x, locate interval (binary count)
        const float xv = x[(size_t)(rowb + lane) * DFEAT + d];
        int j = 0;
        #pragma unroll
        for (int st = 128; st > 0; st >>= 1)
            if (j + st <= H && kns[j + st - 1] <= xv) j += st;

        __syncwarp();
        // k-split evaluation: per row, lanes cover 128 k's (4 each, float4)
        #pragma unroll 4
        for (int r = 0; r < 32; ++r) {
            const float xr = __shfl_sync(0xffffffffu, xv, r);
            const int   jr = __shfl_sync(0xffffffffu, j,  r);
            const float4 Pv =
                reinterpret_cast<const float4*>(tabs + jr * (2 * H))[lane];
            const float4 Qv =
                reinterpret_cast<const float4*>(tabs + jr * (2 * H) + H)[lane];
            const float h0 = fmaxf(fmaf(xr, Pv.x, Qv.x), 0.f);
            const float h1 = fmaxf(fmaf(xr, Pv.y, Qv.y), 0.f);
            const float h2 = fmaxf(fmaf(xr, Pv.z, Qv.z), 0.f);
            const float h3 = fmaxf(fmaf(xr, Pv.w, Qv.w), 0.f);
            float pr = h0 * w3v.x;
            pr = fmaf(h1, w3v.y, pr);
            pr = fmaf(h2, w3v.z, pr);
            pr = fmaf(h3, w3v.w, pr);
            tr[r * 33 + lane] = pr;           // partial of row r by this lane
        }
        __syncwarp();

        // lane L reduces row L (conflict-free: stride 33)
        float sum = b3d;
        #pragma unroll
        for (int i = 0; i < 32; ++i) sum += tr[lane * 33 + i];
        atomicAdd(out + rowb + lane, sum);
        __syncwarp();                          // protect tr before next batch
    }
}

extern "C" void kernel_launch(void* const* d_in, const int* in_sizes, int n_in,
                              void* d_out, int out_size) {
    const float* x  = (const float*)d_in[0];
    const float* W1 = (const float*)d_in[1];
    const float* b1 = (const float*)d_in[2];
    const float* W2 = (const float*)d_in[3];
    const float* b2 = (const float*)d_in[4];
    const float* W3 = (const float*)d_in[5];
    const float* b3 = (const float*)d_in[6];
    float* out = (float*)d_out;

    cudaFuncSetAttribute(kan_precompute,
                         cudaFuncAttributeMaxDynamicSharedMemorySize, PRE_SMEM);
    cudaFuncSetAttribute(kan_main,
                         cudaFuncAttributeMaxDynamicSharedMemorySize, MAIN_SMEM);

    cudaMemsetAsync(d_out, 0, (size_t)out_size * sizeof(float), 0);
    kan_precompute<<<dim3(DFEAT, 8), 512, PRE_SMEM>>>(W1, b1, W2, b2);
    kan_main<<<DFEAT * SPLITS, 256, MAIN_SMEM>>>(x, W3, b3, out);
}

// round 10
// speedup vs baseline: 1.8920x; 1.1992x over previous
#include <cuda_runtime.h>
#include <cuda_fp16.h>
#include <cstdint>

constexpr int NROWS  = 65536;
constexpr int DFEAT  = 32;
constexpr int H      = 128;
constexpr int NJ     = H + 1;          // 129 intervals
constexpr int SPLITS = 32;
constexpr int RPB    = NROWS / SPLITS; // 2048 rows per main CTA

// persistent scratch (static device globals — no runtime allocation)
__device__ uint32_t g_tabh[DFEAT][NJ][H];  // half2(P_k, Q_k+b2_k) per [d][j][k]
__device__ float    g_kn [DFEAT][H];       // sorted knees per feature

__device__ __forceinline__ uint32_t h2u(__half2 h) {
    return *reinterpret_cast<uint32_t*>(&h);
}
__device__ __forceinline__ __half2 u2h(uint32_t u) {
    return *reinterpret_cast<__half2*>(&u);
}

// ---------------- precompute: build interval tables (fp16 packed) ----------
// grid (32, 8): d = blockIdx.x, interval-chunk = blockIdx.y (17 intervals)
__global__ void __launch_bounds__(512)
kan_precompute(const float* __restrict__ W1, const float* __restrict__ b1,
               const float* __restrict__ W2, const float* __restrict__ b2)
{
    extern __shared__ float ps[];
    float* W2s = ps;               // 16384 floats (64 KB)
    float* w1s = ps + H * H;       // 128
    float* b1s = w1s + H;          // 128
    float* b2s = b1s + H;          // 128
    float* kns = b2s + H;          // 128 (sorted knees)

    const int d   = blockIdx.x;
    const int jc  = blockIdx.y;
    const int tid = threadIdx.x;

    const float* w2d = W2 + (size_t)d * H * H;
    for (int i = tid; i < H * H / 4; i += 512)
        reinterpret_cast<float4*>(W2s)[i] =
            reinterpret_cast<const float4*>(w2d)[i];
    for (int i = tid; i < H; i += 512) {
        w1s[i] = W1[d * H + i];
        b1s[i] = b1[d * H + i];
        b2s[i] = b2[d * H + i];
    }
    __syncthreads();

    // knees + O(n^2) rank sort (exact, ties broken by index)
    if (tid < H) {
        const float w = w1s[tid], bb = b1s[tid];
        const float t = (w != 0.f) ? (-bb / w) : 3.0e38f;
        int rank = 0;
        for (int c = 0; c < H; ++c) {
            const float wc = w1s[c], bc = b1s[c];
            const float tc = (wc != 0.f) ? (-bc / wc) : 3.0e38f;
            rank += (tc < t) || ((tc == t) && (c < tid));
        }
        kns[rank] = t;
    }
    __syncthreads();
    if (jc == 0)
        for (int i = tid; i < H; i += 512) g_kn[d][i] = kns[i];

    // build P/Q for intervals in this chunk via midpoint evaluation
    const int j0 = jc * 17;
    const int j1 = min(NJ, j0 + 17);
    for (int idx = tid; idx < (j1 - j0) * H; idx += 512) {
        const int j = j0 + idx / H;
        const int k = idx - (idx / H) * H;
        float m;
        if (j == 0)       m = kns[0] - 1.0f;
        else if (j == H)  m = kns[H - 1] + 1.0f;
        else              m = 0.5f * (kns[j - 1] + kns[j]);
        float P = 0.f, Q = 0.f;
        #pragma unroll 4
        for (int c = 0; c < H; ++c) {
            const bool act = (m * w1s[c] + b1s[c]) > 0.f;
            const float wv = W2s[c * H + k];
            P = fmaf(act ? w1s[c] : 0.f, wv, P);
            Q = fmaf(act ? b1s[c] : 0.f, wv, Q);
        }
        g_tabh[d][j][k] = h2u(__floats2half2_rn(P, Q + b2s[k]));
    }
}

// ---------------- main: interval lookup + 128 fp16-table FMA ---------------
// SMEM floats: tab 16512 (as u32) | kns 128 | trans 8*32*33 | stage 8*32*2
constexpr int SM_TAB    = 0;
constexpr int SM_KN     = NJ * H;                 // 16512
constexpr int SM_TR     = SM_KN + H;              // 16640
constexpr int SM_ST     = SM_TR + 8 * 32 * 33;    // 25088
constexpr int SM_FLOATS = SM_ST + 8 * 32 * 2;     // 25600
constexpr int MAIN_SMEM = SM_FLOATS * 4;          // 102400 B (x2 = 200 KB)
constexpr int PRE_SMEM  = (H * H + 4 * H) * 4;    // 67584 B

__global__ void __launch_bounds__(256, 2)
kan_main(const float* __restrict__ x, const float* __restrict__ W3,
         const float* __restrict__ b3, float* __restrict__ out)
{
    extern __shared__ float s[];
    uint32_t* tabs = reinterpret_cast<uint32_t*>(s + SM_TAB);
    float*    kns  = s + SM_KN;
    float*    tran = s + SM_TR;
    float2*   stg  = reinterpret_cast<float2*>(s + SM_ST);

    const int tid   = threadIdx.x;
    const int d     = blockIdx.x & (DFEAT - 1);  // d fastest -> x L2 reuse
    const int split = blockIdx.x >> 5;
    const int n0    = split * RPB;
    const int lane  = tid & 31, w = tid >> 5;

    // load this feature's packed table + knees into SMEM
    {
        const uint4* src = reinterpret_cast<const uint4*>(&g_tabh[d][0][0]);
        uint4* dst = reinterpret_cast<uint4*>(tabs);
        for (int i = tid; i < NJ * H / 4; i += 256) dst[i] = src[i];
        for (int i = tid; i < H; i += 256) kns[i] = g_kn[d][i];
    }
    __syncthreads();

    const float4 w3v = reinterpret_cast<const float4*>(W3 + d * H)[lane];
    const float  b3d = b3[d];
    float*  tr = tran + w * (32 * 33);
    float2* st = stg  + w * 32;

    for (int b = 0; b < RPB / 256; ++b) {     // 8 batches of 32 rows per warp
        const int rowb = n0 + (b * 8 + w) * 32;

        // each lane owns one row: load x, locate interval (binary count)
        const float xv = x[(size_t)(rowb + lane) * DFEAT + d];
        int j = 0;
        #pragma unroll
        for (int stp = 128; stp > 0; stp >>= 1)
            if (j + stp <= H && kns[j + stp - 1] <= xv) j += stp;

        // stage (x, table u32-offset) for warp-broadcast reads
        st[lane] = make_float2(xv, __int_as_float(j * H));
        __syncwarp();

        // k-split evaluation: per row r, lanes cover 128 k's (4 each)
        #pragma unroll 4
        for (int r = 0; r < 32; ++r) {
            const float2 sv = st[r];
            const float  xr  = sv.x;
            const int    off = __float_as_int(sv.y);
            const uint4  pv  = *reinterpret_cast<const uint4*>(
                                   tabs + off + lane * 4);
            const float2 f0 = __half22float2(u2h(pv.x));
            const float2 f1 = __half22float2(u2h(pv.y));
            const float2 f2 = __half22float2(u2h(pv.z));
            const float2 f3 = __half22float2(u2h(pv.w));
            const float h0 = fmaxf(fmaf(xr, f0.x, f0.y), 0.f);
            const float h1 = fmaxf(fmaf(xr, f1.x, f1.y), 0.f);
            const float h2 = fmaxf(fmaf(xr, f2.x, f2.y), 0.f);
            const float h3 = fmaxf(fmaf(xr, f3.x, f3.y), 0.f);
            float pr = h0 * w3v.x;
            pr = fmaf(h1, w3v.y, pr);
            pr = fmaf(h2, w3v.z, pr);
            pr = fmaf(h3, w3v.w, pr);
            tr[r * 33 + lane] = pr;           // partial of row r by this lane
        }
        __syncwarp();

        // lane L reduces row L (conflict-free: stride 33)
        float sum = b3d;
        #pragma unroll
        for (int i = 0; i < 32; ++i) sum += tr[lane * 33 + i];
        atomicAdd(out + rowb + lane, sum);
        __syncwarp();                          // protect tr/st before next batch
    }
}

extern "C" void kernel_launch(void* const* d_in, const int* in_sizes, int n_in,
                              void* d_out, int out_size) {
    const float* x  = (const float*)d_in[0];
    const float* W1 = (const float*)d_in[1];
    const float* b1 = (const float*)d_in[2];
    const float* W2 = (const float*)d_in[3];
    const float* b2 = (const float*)d_in[4];
    const float* W3 = (const float*)d_in[5];
    const float* b3 = (const float*)d_in[6];
    float* out = (float*)d_out;

    cudaFuncSetAttribute(kan_precompute,
                         cudaFuncAttributeMaxDynamicSharedMemorySize, PRE_SMEM);
    cudaFuncSetAttribute(kan_main,
                         cudaFuncAttributeMaxDynamicSharedMemorySize, MAIN_SMEM);

    cudaMemsetAsync(d_out, 0, (size_t)out_size * sizeof(float), 0);
    kan_precompute<<<dim3(DFEAT, 8), 512, PRE_SMEM>>>(W1, b1, W2, b2);
    kan_main<<<DFEAT * SPLITS, 256, MAIN_SMEM>>>(x, W3, b3, out);
}

// round 11
// speedup vs baseline: 2.2839x; 1.2071x over previous
#include <cuda_runtime.h>
#include <cuda_fp16.h>
#include <cstdint>

constexpr int NROWS  = 65536;
constexpr int DFEAT  = 32;
constexpr int H      = 128;
constexpr int NJ     = H + 1;          // 129 intervals
constexpr int SPLITS = 32;
constexpr int RPB    = NROWS / SPLITS; // 2048 rows per main CTA

// persistent scratch (static device globals — no runtime allocation)
// per (d, j, lane): uint4 {P01, P23, Q01, Q23} covering k = 4*lane .. 4*lane+3
__device__ uint4 g_tab4[DFEAT][NJ][32];
__device__ float g_kn  [DFEAT][H];

__device__ __forceinline__ uint32_t h2u(__half2 h) {
    return *reinterpret_cast<uint32_t*>(&h);
}
__device__ __forceinline__ __half2 u2h(uint32_t u) {
    return *reinterpret_cast<__half2*>(&u);
}

// ---------------- precompute: incremental interval tables ----------------
// one CTA per feature d; 128 threads. Warp w builds interval range
// [j0_w, jend_w] via midpoint init + one-knee-flip incremental updates.
constexpr int PRE_SMEM = (H * H + 7 * H) * 4;   // W2 + 7 small arrays

__global__ void __launch_bounds__(128)
kan_precompute(const float* __restrict__ W1, const float* __restrict__ b1,
               const float* __restrict__ W2, const float* __restrict__ b2)
{
    extern __shared__ float ps[];
    float* W2s = ps;               // 16384
    float* w1s = W2s + H * H;      // 128
    float* b1s = w1s + H;
    float* b2s = b1s + H;
    float* kns = b2s + H;          // sorted knees
    float* sus = kns + H;          // |w1_c| in knee-sorted order
    float* svs = sus + H;          // sign(w1_c)*b1_c in knee-sorted order
    int*   cix = reinterpret_cast<int*>(svs + H);  // unit index per rank

    const int d = blockIdx.x, tid = threadIdx.x;

    const float* w2d = W2 + (size_t)d * H * H;
    for (int i = tid; i < H * H / 4; i += 128)
        reinterpret_cast<float4*>(W2s)[i] =
            reinterpret_cast<const float4*>(w2d)[i];
    w1s[tid] = W1[d * H + tid];
    b1s[tid] = b1[d * H + tid];
    b2s[tid] = b2[d * H + tid];
    __syncthreads();

    // knee + exact rank sort (thread = unit)
    {
        const float w = w1s[tid], bb = b1s[tid];
        const float t = (w != 0.f) ? (-bb / w) : 3.0e38f;
        int rank = 0;
        for (int c = 0; c < H; ++c) {
            const float wc = w1s[c], bc = b1s[c];
            const float tc = (wc != 0.f) ? (-bc / wc) : 3.0e38f;
            rank += (tc < t) || ((tc == t) && (c < tid));
        }
        kns[rank] = t;
        cix[rank] = tid;
        sus[rank] = fabsf(w);
        svs[rank] = (w > 0.f) ? bb : -bb;   // sign(w)*b1 (w==0 never crossed)
    }
    __syncthreads();
    g_kn[d][tid] = kns[tid];

    const int warp = tid >> 5, lane = tid & 31;
    const int j0   = (warp == 0) ? 0 : warp * 32 + 1;
    const int jend = warp * 32 + 32;       // warp0: 0..32, w: 32w+1..32w+32
    const int kb   = lane * 4;

    // midpoint of interval j0 (overflow-safe form)
    float m;
    if (j0 == 0) m = kns[0] - 1.0f;
    else         m = kns[j0 - 1] + 0.5f * (kns[j0] - kns[j0 - 1]);

    float P[4] = {0.f, 0.f, 0.f, 0.f};
    float Q[4] = {b2s[kb], b2s[kb + 1], b2s[kb + 2], b2s[kb + 3]};
    for (int c = 0; c < H; ++c) {
        const float wc = w1s[c], bc = b1s[c];
        if (m * wc + bc > 0.f) {
            const float4 wv = *reinterpret_cast<const float4*>(W2s + c * H + kb);
            P[0] = fmaf(wc, wv.x, P[0]); Q[0] = fmaf(bc, wv.x, Q[0]);
            P[1] = fmaf(wc, wv.y, P[1]); Q[1] = fmaf(bc, wv.y, Q[1]);
            P[2] = fmaf(wc, wv.z, P[2]); Q[2] = fmaf(bc, wv.z, Q[2]);
            P[3] = fmaf(wc, wv.w, P[3]); Q[3] = fmaf(bc, wv.w, Q[3]);
        }
    }
    auto store = [&](int j) {
        uint4 u;
        u.x = h2u(__floats2half2_rn(P[0], P[1]));
        u.y = h2u(__floats2half2_rn(P[2], P[3]));
        u.z = h2u(__floats2half2_rn(Q[0], Q[1]));
        u.w = h2u(__floats2half2_rn(Q[2], Q[3]));
        g_tab4[d][j][lane] = u;
    };
    store(j0);
    for (int j = j0 + 1; j <= jend; ++j) {
        const int   c  = cix[j - 1];
        const float uu = sus[j - 1], vv = svs[j - 1];
        const float4 wv = *reinterpret_cast<const float4*>(W2s + c * H + kb);
        P[0] = fmaf(uu, wv.x, P[0]); Q[0] = fmaf(vv, wv.x, Q[0]);
        P[1] = fmaf(uu, wv.y, P[1]); Q[1] = fmaf(vv, wv.y, Q[1]);
        P[2] = fmaf(uu, wv.z, P[2]); Q[2] = fmaf(vv, wv.z, Q[2]);
        P[3] = fmaf(uu, wv.w, P[3]); Q[3] = fmaf(vv, wv.w, Q[3]);
        store(j);
    }
}

// ---------------- main: interval lookup + half2-native evaluation ----------
// SMEM floats: tab4 16512 | kns 128 | trans 8448 | stage 512 = 25600 (100 KB)
constexpr int SM_TAB    = 0;
constexpr int SM_KN     = NJ * 32 * 4;            // 16512 u32
constexpr int SM_TR     = SM_KN + H;              // 16640
constexpr int SM_ST     = SM_TR + 8 * 32 * 33;    // 25088
constexpr int SM_FLOATS = SM_ST + 8 * 32 * 2;     // 25600
constexpr int MAIN_SMEM = SM_FLOATS * 4;          // 102400 B (x2 = 200 KB)

__global__ void __launch_bounds__(256, 2)
kan_main(const float* __restrict__ x, const float* __restrict__ W3,
         const float* __restrict__ b3, float* __restrict__ out)
{
    extern __shared__ float s[];
    uint4* tab4 = reinterpret_cast<uint4*>(s + SM_TAB);
    float* kns  = s + SM_KN;
    float* tran = s + SM_TR;
    uint2* stg  = reinterpret_cast<uint2*>(s + SM_ST);

    const int tid   = threadIdx.x;
    const int d     = blockIdx.x & (DFEAT - 1);  // d fastest -> x L2 reuse
    const int split = blockIdx.x >> 5;
    const int n0    = split * RPB;
    const int lane  = tid & 31, w = tid >> 5;

    // load this feature's packed table + knees into SMEM
    {
        const uint4* src = &g_tab4[d][0][0];
        for (int i = tid; i < NJ * 32; i += 256) tab4[i] = src[i];
        for (int i = tid; i < H; i += 256) kns[i] = g_kn[d][i];
    }
    __syncthreads();

    // per-lane W3 pairs (half2) for k = 4*lane .. 4*lane+3
    const float4 w3f = reinterpret_cast<const float4*>(W3 + d * H)[lane];
    const __half2 w301 = __floats2half2_rn(w3f.x, w3f.y);
    const __half2 w323 = __floats2half2_rn(w3f.z, w3f.w);
    const float   b3d  = b3[d];
    const __half2 zero2 = __float2half2_rn(0.f);

    float* tr = tran + w * (32 * 33);
    uint2* st = stg + w * 32;

    for (int b = 0; b < RPB / 256; ++b) {     // 8 batches of 32 rows per warp
        const int rowb = n0 + (b * 8 + w) * 32;

        // each lane owns one row: load x, locate interval (binary count)
        const float xv = x[(size_t)(rowb + lane) * DFEAT + d];
        int j = 0;
        #pragma unroll
        for (int stp = 128; stp > 0; stp >>= 1)
            if (j + stp <= H && kns[j + stp - 1] <= xv) j += stp;

        // stage packed x (half2) and uint4-offset for warp-broadcast reads
        st[lane] = make_uint2(h2u(__half2half2(__float2half_rn(xv))),
                              (uint32_t)(j * 32));
        __syncwarp();

        // per row r, lanes cover 128 k's (4 each, half2-native)
        #pragma unroll 4
        for (int r = 0; r < 32; ++r) {
            const uint2 sv = st[r];
            const __half2 x2 = u2h(sv.x);
            const uint4 pv = tab4[sv.y + lane];
            const __half2 h01 = __hmax2(__hfma2(x2, u2h(pv.x), u2h(pv.z)), zero2);
            const __half2 h23 = __hmax2(__hfma2(x2, u2h(pv.y), u2h(pv.w)), zero2);
            const __half2 pr2 = __hfma2(h01, w301, __hmul2(h23, w323));
            const float2  pf  = __half22float2(pr2);
            tr[r * 33 + lane] = pf.x + pf.y;   // partial of row r by this lane
        }
        __syncwarp();

        // lane L reduces row L (conflict-free: stride 33)
        float sum = b3d;
        #pragma unroll
        for (int i = 0; i < 32; ++i) sum += tr[lane * 33 + i];
        atomicAdd(out + rowb + lane, sum);
        __syncwarp();                          // protect tr/st before next batch
    }
}

extern "C" void kernel_launch(void* const* d_in, const int* in_sizes, int n_in,
                              void* d_out, int out_size) {
    const float* x  = (const float*)d_in[0];
    const float* W1 = (const float*)d_in[1];
    const float* b1 = (const float*)d_in[2];
    const float* W2 = (const float*)d_in[3];
    const float* b2 = (const float*)d_in[4];
    const float* W3 = (const float*)d_in[5];
    const float* b3 = (const float*)d_in[6];
    float* out = (float*)d_out;

    cudaFuncSetAttribute(kan_precompute,
                         cudaFuncAttributeMaxDynamicSharedMemorySize, PRE_SMEM);
    cudaFuncSetAttribute(kan_main,
                         cudaFuncAttributeMaxDynamicSharedMemorySize, MAIN_SMEM);

    cudaMemsetAsync(d_out, 0, (size_t)out_size * sizeof(float), 0);
    kan_precompute<<<DFEAT, 128, PRE_SMEM>>>(W1, b1, W2, b2);
    kan_main<<<DFEAT * SPLITS, 256, MAIN_SMEM>>>(x, W3, b3, out);
}